// round 17
// baseline (speedup 1.0000x reference)
#include <cuda_runtime.h>
#include <cstdint>

#define KDIM     256
#define NCOLS    40          // 10 classes * 4 centroids
#define NCLASSES 10
#define KCENT    4
#define BM       256         // rows per CTA tile: 8 warps x 32 rows
#define NTHREADS 256
#define NCHUNK   8           // 8 chunks of K=32
#define STAGES   4           // cp.async pipeline depth (per warp)

// Dynamic tile queue (self-resetting; no allocations).
__device__ int g_ctr  = 0;
__device__ int g_done = 0;

__device__ __forceinline__ void cp16(uint32_t dst, const float* src) {
    asm volatile("cp.async.cg.shared.global [%0], [%1], 16;"
                 :: "r"(dst), "l"(src) : "memory");
}
__device__ __forceinline__ void cp_commit() {
    asm volatile("cp.async.commit_group;" ::: "memory");
}
__device__ __forceinline__ void cp_wait3() {
    asm volatile("cp.async.wait_group 3;" ::: "memory");
}
__device__ __forceinline__ float tf32r(float x) {
    uint32_t u;
    asm("cvt.rna.tf32.f32 %0, %1;" : "=r"(u) : "f"(x));
    return __uint_as_float(u);
}

// ---------------------------------------------------------------------------
// Hot kernel: persistent CTAs (1/SM), 8 warps (R15 hot loop, unchanged).
// NEW: dynamic work stealing — tiles come from a global atomic queue, so
// fast SMs absorb the between-SM spread instead of idling at the end.
// Warp-private depth-4 cp.async pipeline for A; in-CTA B prep; conflict-free
// LDS.128; mma m16n8k8 tf32; fused 1 - max_k epilogue.
// smem: A 8 warps * 4 stages * 4KB = 128KB + B 40KB = 168KB.
// ---------------------------------------------------------------------------
extern __shared__ float4 smem4[];

__global__ void __launch_bounds__(NTHREADS, 1)
gemm_kernel(const float* __restrict__ codes,
            const float* __restrict__ cents,
            float* __restrict__ out, int ntiles) {
    float4* const Asm = smem4;            // 8192 float4 (128 KB)
    float4* const Bsm = smem4 + 8192;     // 2560 float4 (40 KB)
    __shared__ int s_t0, s_t1, s_next;

    const int tid  = threadIdx.x;
    const int lane = tid & 31;
    const int warp = tid >> 5;
    const int g = lane >> 2;     // 0..7
    const int q = lane & 3;      // 0..3

    // Fetch the first two tiles (launcher guarantees 2*gridDim <= ntiles).
    if (tid == 0) {
        s_t0 = atomicAdd(&g_ctr, 1);
        s_t1 = atomicAdd(&g_ctr, 1);
    }
    __syncthreads();
    int tcur = s_t0, tnext = s_t1;

    // byte address of this thread's slot in stage 0 of its warp region
    const uint32_t abase =
        (uint32_t)__cvta_generic_to_shared(Asm) +
        ((uint32_t)(warp * STAGES) * 8 * 32 + lane) * 16u;
    // 32-bit element offsets (8192 tiles * 64K < 2^32)
    const uint32_t boffw = (uint32_t)(warp * 32 + g) * KDIM + (uint32_t)(4 * q);

    // Issue all 8 cp.asyncs for (tile, k-chunk) into stage st, 1 group.
    auto issue = [&](int tile, int chunk, int st) {
        if (tile >= ntiles) tile = ntiles - 1;   // clamp at drain (dup write)
        const float* ap = codes + (boffw + (uint32_t)tile * (BM * KDIM)
                                   + (uint32_t)(chunk * 32));
        const uint32_t dst = abase + (uint32_t)st * (8 * 32 * 16);
        #pragma unroll
        for (int j = 0; j < 4; j++)
            #pragma unroll
            for (int i = 0; i < 2; i++)
                cp16(dst + (uint32_t)((j * 2 + i) * 32) * 16,
                     ap + j * 8 * KDIM + i * 16);
        cp_commit();
    };

    // Prologue: start the A pipeline before anything else touches memory.
    issue(tcur, 0, 0); issue(tcur, 1, 1); issue(tcur, 2, 2);

    // In-CTA B prep (overlapped with the A prologue), identical to R15.
    {
        const int sl  = (lane >> 3) * 5;
        const int ii  = (lane >> 2) & 1;
        const int col = (lane & 3);
        #pragma unroll
        for (int vv = 0; vv < 5; vv++) {
            const int v = warp * 5 + vv;
            const float4* src4 = reinterpret_cast<const float4*>(cents + v * KDIM);
            const float4 v0 = src4[lane];
            const float4 v1 = src4[lane + 32];
            float s = v0.x * v0.x + v0.y * v0.y + v0.z * v0.z + v0.w * v0.w
                    + v1.x * v1.x + v1.y * v1.y + v1.z * v1.z + v1.w * v1.w;
            #pragma unroll
            for (int off = 16; off; off >>= 1)
                s += __shfl_xor_sync(0xffffffffu, s, off);
            const float inv = 1.f / fmaxf(sqrtf(s), 1e-12f);
            const int nt = v >> 3;
            const int gg = v & 7;
            float4 o0, o1;
            o0.x = tf32r(v0.x * inv); o0.y = tf32r(v0.y * inv);
            o0.z = tf32r(v0.z * inv); o0.w = tf32r(v0.w * inv);
            o1.x = tf32r(v1.x * inv); o1.y = tf32r(v1.y * inv);
            o1.z = tf32r(v1.z * inv); o1.w = tf32r(v1.w * inv);
            Bsm[((sl + nt) * 2 + ii) * 32 + gg * 4 + col] = o0;       // c
            Bsm[((sl + 20 + nt) * 2 + ii) * 32 + gg * 4 + col] = o1;  // c+4
        }
    }
    __syncthreads();

    const float4* const aread = Asm + (warp * STAGES) * 8 * 32 + lane;
    int ist = 3;                 // next stage to fill
    int rst = 0;                 // next stage to read

    while (tcur < ntiles) {
        if (tid == 0) s_next = atomicAdd(&g_ctr, 1);   // prefetch next tile id

        float acc[2][5][4];
        #pragma unroll
        for (int t = 0; t < 2; t++)
            #pragma unroll
            for (int n = 0; n < 5; n++)
                #pragma unroll
                for (int j = 0; j < 4; j++) acc[t][n][j] = 0.f;

        #pragma unroll
        for (int c = 0; c < NCHUNK; c++) {
            issue(c < 5 ? tcur : tnext, (c + 3) & 7, ist);
            ist = (ist + 1) & 3;
            cp_wait3();                    // this chunk complete

            float4 A4[4][2];
            #pragma unroll
            for (int j = 0; j < 4; j++)
                #pragma unroll
                for (int i = 0; i < 2; i++)
                    A4[j][i] = aread[(rst * 8 + j * 2 + i) * 32];
            rst = (rst + 1) & 3;

            #pragma unroll
            for (int nt = 0; nt < 5; nt++) {
                const float4 wb0 = Bsm[((c * 5 + nt) * 2 + 0) * 32 + lane];
                const float4 wb1 = Bsm[((c * 5 + nt) * 2 + 1) * 32 + lane];
                #pragma unroll
                for (int m = 0; m < 4; m++) {
                    const float4 wb = (m < 2) ? wb0 : wb1;
                    const uint32_t b0 = __float_as_uint((m & 1) ? wb.z : wb.x);
                    const uint32_t b1 = __float_as_uint((m & 1) ? wb.w : wb.y);
                    #pragma unroll
                    for (int t = 0; t < 2; t++) {
                        const float4 p0 = A4[2 * t][m >> 1];
                        const float4 p1 = A4[2 * t + 1][m >> 1];
                        const uint32_t a0 = __float_as_uint((m & 1) ? p0.z : p0.x);
                        const uint32_t a1 = __float_as_uint((m & 1) ? p1.z : p1.x);
                        const uint32_t a2 = __float_as_uint((m & 1) ? p0.w : p0.y);
                        const uint32_t a3 = __float_as_uint((m & 1) ? p1.w : p1.y);
                        asm volatile(
                            "mma.sync.aligned.m16n8k8.row.col.f32.tf32.tf32.f32 "
                            "{%0,%1,%2,%3}, {%4,%5,%6,%7}, {%8,%9}, {%0,%1,%2,%3};"
                            : "+f"(acc[t][nt][0]), "+f"(acc[t][nt][1]),
                              "+f"(acc[t][nt][2]), "+f"(acc[t][nt][3])
                            : "r"(a0), "r"(a1), "r"(a2), "r"(a3),
                              "r"(b0), "r"(b1));
                    }
                }
            }
        }

        // Epilogue for tile tcur.
        const long row0 = (long)tcur * BM + warp * 32 + g;
        float* const obase = out + row0 * NCLASSES;
        #pragma unroll
        for (int t = 0; t < 2; t++) {
            #pragma unroll
            for (int nt = 0; nt < 5; nt++) {
                float m0 = fmaxf(acc[t][nt][0], acc[t][nt][1]);
                float m1 = fmaxf(acc[t][nt][2], acc[t][nt][3]);
                m0 = fmaxf(m0, __shfl_xor_sync(0xffffffffu, m0, 1));
                m1 = fmaxf(m1, __shfl_xor_sync(0xffffffffu, m1, 1));
                const int cls = nt * 2 + (q >> 1);
                if ((q & 1) == 0) {
                    __stcs(obase + (16 * t) * NCLASSES + cls, 1.f - m0);
                    __stcs(obase + (16 * t + 8) * NCLASSES + cls, 1.f - m1);
                }
            }
        }

        __syncthreads();                 // s_next write visible to all
        tcur = tnext; tnext = s_next;
        __syncthreads();                 // protect s_next before next fetch
    }

    // Self-reset of the queue (last CTA), deterministic across graph replays.
    if (tid == 0) {
        __threadfence();
        const int d = atomicAdd(&g_done, 1);
        if (d == (int)gridDim.x - 1) {
            g_ctr = 0;
            g_done = 0;
            __threadfence();
        }
    }
}

// ---------------------------------------------------------------------------
// Tail: remaining (< BM) rows, plain fp32, self-contained.
// ---------------------------------------------------------------------------
__global__ void tail_kernel(const float* __restrict__ codes,
                            const float* __restrict__ cents,
                            float* __restrict__ out,
                            long rbase, int nrows) {
    const long row = rbase + blockIdx.x * blockDim.x + threadIdx.x;
    if (row >= nrows) return;
    const float* a = codes + row * KDIM;
    float best[NCLASSES];
    #pragma unroll
    for (int c = 0; c < NCLASSES; c++) best[c] = -1e30f;
    for (int v = 0; v < NCOLS; v++) {
        const float* bp = cents + v * KDIM;
        float nrm = 0.f, s = 0.f;
        for (int k = 0; k < KDIM; k++) {
            nrm += bp[k] * bp[k];
            s   += a[k] * bp[k];
        }
        s *= 1.f / fmaxf(sqrtf(nrm), 1e-12f);
        const int c = v / KCENT;
        best[c] = fmaxf(best[c], s);
    }
    #pragma unroll
    for (int c = 0; c < NCLASSES; c++)
        out[row * NCLASSES + c] = 1.f - best[c];
}

// ---------------------------------------------------------------------------
extern "C" void kernel_launch(void* const* d_in, const int* in_sizes, int n_in,
                              void* d_out, int out_size) {
    const float* codes = (const float*)d_in[0];   // (B, 256) f32
    const float* cents = (const float*)d_in[1];   // (10, 4, 256) f32
    float* out = (float*)d_out;                   // (B, 10) f32

    const int nrows  = in_sizes[0] / KDIM;
    const int ntiles = nrows / BM;
    const int tail   = nrows - ntiles * BM;

    const int smem_bytes = (8192 + 2560) * (int)sizeof(float4);  // 172032

    cudaFuncSetAttribute(gemm_kernel,
                         cudaFuncAttributeMaxDynamicSharedMemorySize,
                         smem_bytes);

    int nsm = 0;
    cudaDeviceGetAttribute(&nsm, cudaDevAttrMultiProcessorCount, 0);
    if (nsm <= 0) nsm = 148;

    if (ntiles > 0) {
        // ensure both prologue fetches per CTA are valid tiles
        int grid = ntiles / 2;
        if (grid > nsm) grid = nsm;
        if (grid < 1) grid = 1;
        gemm_kernel<<<grid, NTHREADS, smem_bytes>>>(codes, cents, out, ntiles);
    }
    if (tail > 0) {
        const int tb = (tail + 255) / 256;
        tail_kernel<<<tb, 256>>>(codes, cents, out, (long)ntiles * BM, nrows);
    }
}